// round 10
// baseline (speedup 1.0000x reference)
#include <cuda_runtime.h>
#include <cuda_bf16.h>
#include <cstdint>

#define BATCH 4096
#define DIM   512
#define HIDN  2048
#define NSTEPS 20

#define BM 64
#define BN 128
#define BK 32
#define MI 2
#define NI 4
#define SPITCH 40          // bf16 per smem row (80B) — 16B-aligned, LDSM conflict-free
#define ROWB (SPITCH*2)

#define ASZ (BM*ROWB)      // 5120
#define BSZ (BN*ROWB)      // 10240
#define SMA 1024
#define SMB (SMA + 3*ASZ)
#define SMEM_TOT (SMB + 3*BSZ)   // 47104

// ---------------- persistent scratch ----------------
__device__ __align__(256) float          g_zcur[BATCH*DIM];
__device__ __align__(256) float          g_zacc[BATCH*DIM];
__device__ __align__(256) float          g_kp[4][BATCH*DIM];   // split-K partials
__device__ __align__(256) __nv_bfloat16  g_zb[BATCH*DIM];
__device__ __align__(256) __nv_bfloat16  g_hid[BATCH*HIDN];
__device__ __align__(256) __nv_bfloat16  g_w1t[HIDN*DIM];      // [n][k]
__device__ __align__(256) float          g_w1last[HIDN];
__device__ __align__(256) __nv_bfloat16  g_w2t[DIM*HIDN];      // [n][k]
__device__ int                           g_cnt[256];           // split-K tile counters (self-resetting)

// ---------------- converts ----------------
__global__ void convert_z(const float* __restrict__ z0){
    int i = blockIdx.x*blockDim.x + threadIdx.x;
    if (i < BATCH*DIM){
        float v = z0[i];
        g_zcur[i] = v;
        g_zb[i]   = __float2bfloat16(v);
    }
}
__global__ void convert_w(const float* __restrict__ W1, const float* __restrict__ W2){
    int i = blockIdx.x*blockDim.x + threadIdx.x;
    if (i < HIDN*DIM){
        int n = i / DIM, k = i % DIM;
        g_w1t[i] = __float2bfloat16(W1[(size_t)k*HIDN + n]);
    }
    if (i < DIM*HIDN){
        int n = i / HIDN, k = i % HIDN;
        g_w2t[i] = __float2bfloat16(W2[(size_t)k*DIM + n]);
    }
    if (i < HIDN) g_w1last[i] = W1[(size_t)DIM*HIDN + i];
}

// ---------------- helpers ----------------
__device__ __forceinline__ void cpa16(uint32_t s, const void* g){
    asm volatile("cp.async.cg.shared.global [%0], [%1], 16;\n" :: "r"(s), "l"(g));
}
__device__ __forceinline__ void ldsm4(uint32_t& r0, uint32_t& r1, uint32_t& r2, uint32_t& r3,
                                      uint32_t addr){
    asm volatile("ldmatrix.sync.aligned.m8n8.x4.shared.b16 {%0,%1,%2,%3}, [%4];"
                 : "=r"(r0), "=r"(r1), "=r"(r2), "=r"(r3) : "r"(addr));
}
__device__ __forceinline__ uint32_t smem_u32(const void* p){
    uint32_t a;
    asm("{ .reg .u64 t; cvta.to.shared.u64 t, %1; cvt.u32.u64 %0, t; }" : "=r"(a) : "l"(p));
    return a;
}
#define MMA16816(acc, af, bf)                                                     \
    asm volatile(                                                                 \
        "mma.sync.aligned.m16n8k16.row.col.f32.bf16.bf16.f32 "                    \
        "{%0,%1,%2,%3}, {%4,%5,%6,%7}, {%8,%9}, {%0,%1,%2,%3};\n"                 \
        : "+f"(acc[0]), "+f"(acc[1]), "+f"(acc[2]), "+f"(acc[3])                  \
        : "r"(af[0]), "r"(af[1]), "r"(af[2]), "r"(af[3]), "r"(bf[0]), "r"(bf[1]))

// ---------------- fused GEMM ----------------
// CTA 64x128, 256 thr (8 warps: 2M x 4N, warp 32x32), BK=32, 3-stage, K-extent 512.
// epi==0: g_hid = tanh(g_zb @ g_w1t^T + b1 + t*w1last)
// epi==1: g_kp[blockIdx.z] = partial(g_hid @ g_w2t^T); LAST split CTA per tile
//         performs the fused RK4 update for its 64x128 tile.
__global__ void __launch_bounds__(256, 3)
gemm_tc(const float* __restrict__ b1, const float* __restrict__ b2,
        const float* __restrict__ t0p, const float* __restrict__ t1p,
        float* __restrict__ dout,
        int epi, float stepF, float cOff,
        float wcoef, float acoef, int accPrev, int finalStage, int toOut)
{
    extern __shared__ char smem[];
    const uint32_t sb = smem_u32(smem);
    float* biasS = (float*)smem;
    __shared__ int sIsLast;

    const int tid  = threadIdx.x;
    const int lane = tid & 31, w = tid >> 5;
    const int bm = blockIdx.y * BM, bn = blockIdx.x * BN;

    const __nv_bfloat16* A; const __nv_bfloat16* B; int Kd, kOff;
    float* kp = nullptr;
    if (epi == 0){ A = g_zb;  B = g_w1t; Kd = DIM;  kOff = 0; }
    else {
        A = g_hid; B = g_w2t; Kd = HIDN;
        kOff = blockIdx.z * 512;
        kp   = g_kp[blockIdx.z];
    }
    constexpr int NT = 512 / BK;    // 16 for both paths

    const int wm = (w >> 2) * 32;
    const int wn = (w & 3)  * 32;

    const int lr = lane & 7;
    const int lm = (lane >> 3) & 1;
    const int lk = (lane >> 4) & 1;
    const uint32_t aBase = sb + SMA + (uint32_t)((wm + lr + lm*8)*SPITCH + lk*8)*2;
    const uint32_t bBase = sb + SMB + (uint32_t)((wn + lr + lm*8)*SPITCH + lk*8)*2;

    auto loadChunk = [&](int c){
        const int s  = c % 3;
        const int k0 = kOff + c * BK;
        const uint32_t sA = sb + SMA + s*ASZ;
        const uint32_t sB = sb + SMB + s*BSZ;
        {   // A: 64 rows x 4 x 16B = 256 vectors (1 per thread)
            int row = tid >> 2, col = tid & 3;
            cpa16(sA + row*ROWB + col*16, A + (size_t)(bm + row)*Kd + k0 + col*8);
        }
        #pragma unroll
        for (int r = 0; r < 2; r++){   // B: 128 rows x 4 x 16B = 512 vectors
            int v = tid + r*256;
            int row = v >> 2, col = v & 3;
            cpa16(sB + row*ROWB + col*16, B + (size_t)(bn + row)*Kd + k0 + col*8);
        }
        asm volatile("cp.async.commit_group;\n");
    };

    loadChunk(0);
    loadChunk(1);

    const float hh = (__ldg(t1p) - __ldg(t0p)) / (float)NSTEPS;

    // bias -> smem (GEMM1 only)
    if (epi == 0 && tid < BN){
        float t = __ldg(t0p) + (stepF + cOff) * hh;
        biasS[tid] = __ldg(&b1[bn + tid]) + t * g_w1last[bn + tid];
    }

    float acc[MI][NI][4];
    #pragma unroll
    for (int a=0;a<MI;a++)
        #pragma unroll
        for (int b=0;b<NI;b++)
            #pragma unroll
            for (int c=0;c<4;c++) acc[a][b][c] = 0.f;

    for (int kt = 0; kt < NT; kt++){
        if (kt < NT-1) asm volatile("cp.async.wait_group 1;\n");
        else           asm volatile("cp.async.wait_group 0;\n");
        __syncthreads();
        if (kt + 2 < NT) loadChunk(kt + 2);   // writes stage (kt+2)%3 == (kt-1)%3: safe after sync

        const int s = kt % 3;
        const uint32_t aAddr = aBase + s*ASZ;
        const uint32_t bAddr = bBase + s*BSZ;

        #pragma unroll
        for (int kki = 0; kki < 2; kki++){
            const uint32_t koff = (uint32_t)(kki*32);   // 16 bf16 = 32B
            uint32_t af[MI][4], bf[NI][2];
            #pragma unroll
            for (int mi = 0; mi < MI; mi++)
                ldsm4(af[mi][0], af[mi][1], af[mi][2], af[mi][3],
                      aAddr + (uint32_t)(mi*16*ROWB) + koff);
            #pragma unroll
            for (int nh = 0; nh < NI/2; nh++){
                uint32_t r0, r1, r2, r3;
                ldsm4(r0, r1, r2, r3, bAddr + (uint32_t)(nh*16*ROWB) + koff);
                bf[2*nh  ][0] = r0; bf[2*nh  ][1] = r2;
                bf[2*nh+1][0] = r1; bf[2*nh+1][1] = r3;
            }
            #pragma unroll
            for (int mi = 0; mi < MI; mi++)
                #pragma unroll
                for (int ni = 0; ni < NI; ni++)
                    MMA16816(acc[mi][ni], af[mi], bf[ni]);
        }
    }

    // ---------------- epilogue ----------------
    const int g  = lane >> 2;
    const int tq = lane & 3;

    #pragma unroll
    for (int mi = 0; mi < MI; mi++)
        #pragma unroll
        for (int ni = 0; ni < NI; ni++){
            const int colL = wn + ni*8 + tq*2;
            const int col  = bn + colL;
            #pragma unroll
            for (int half = 0; half < 2; half++){
                const int row = bm + wm + mi*16 + g + half*8;
                float v0 = acc[mi][ni][half*2+0];
                float v1 = acc[mi][ni][half*2+1];
                if (epi == 0){
                    v0 += biasS[colL]; v1 += biasS[colL+1];
                    float th0, th1;
                    asm("tanh.approx.f32 %0, %1;" : "=f"(th0) : "f"(v0));
                    asm("tanh.approx.f32 %0, %1;" : "=f"(th1) : "f"(v1));
                    *(__nv_bfloat162*)(&g_hid[(size_t)row*HIDN + col]) =
                        __floats2bfloat162_rn(th0, th1);
                } else {
                    *(float2*)(&kp[(size_t)row*DIM + col]) = make_float2(v0, v1);
                }
            }
        }

    if (epi == 0) return;

    // ---------------- split-K last-CTA fused RK4 reduction ----------------
    __threadfence();
    const int tile = blockIdx.y * gridDim.x + blockIdx.x;   // 64*4 = 256 tiles
    if (tid == 0){
        int old = atomicAdd(&g_cnt[tile], 1);
        sIsLast = (old == 3);
    }
    __syncthreads();
    if (!sIsLast) return;
    if (tid == 0) g_cnt[tile] = 0;   // self-reset for graph replay

    const float wh = wcoef * hh;
    const float ah = acoef * hh;

    // tile = 64 rows x 128 cols = 2048 float4 chunks; 8 per thread
    #pragma unroll
    for (int e = 0; e < 8; e++){
        const int c    = tid + e*256;
        const int row  = bm + (c >> 5);
        const int col  = bn + ((c & 31) << 2);
        const size_t idx = (size_t)row * DIM + col;

        float4 k0 = *(const float4*)(&g_kp[0][idx]);
        float4 k1 = *(const float4*)(&g_kp[1][idx]);
        float4 k2 = *(const float4*)(&g_kp[2][idx]);
        float4 k3 = *(const float4*)(&g_kp[3][idx]);
        const float4 bb = *(const float4*)(&b2[col]);
        float4 k = make_float4(k0.x+k1.x+k2.x+k3.x+bb.x,
                               k0.y+k1.y+k2.y+k3.y+bb.y,
                               k0.z+k1.z+k2.z+k3.z+bb.z,
                               k0.w+k1.w+k2.w+k3.w+bb.w);

        float4 za;
        if (accPrev) za = *(const float4*)(&g_zacc[idx]);
        else         za = make_float4(0.f,0.f,0.f,0.f);
        za.x += wh*k.x; za.y += wh*k.y; za.z += wh*k.z; za.w += wh*k.w;
        *(float4*)(&g_zacc[idx]) = za;

        float4 zc = *(const float4*)(&g_zcur[idx]);
        float4 zn;
        if (finalStage){
            zn = make_float4(zc.x+za.x, zc.y+za.y, zc.z+za.z, zc.w+za.w);
            if (toOut) *(float4*)(&dout[idx]) = zn;
            else       *(float4*)(&g_zcur[idx]) = zn;
        } else {
            zn = make_float4(zc.x+ah*k.x, zc.y+ah*k.y, zc.z+ah*k.z, zc.w+ah*k.w);
        }
        *(__nv_bfloat162*)(&g_zb[idx])   = __floats2bfloat162_rn(zn.x, zn.y);
        *(__nv_bfloat162*)(&g_zb[idx+2]) = __floats2bfloat162_rn(zn.z, zn.w);
    }
}

// ---------------- launcher ----------------
extern "C" void kernel_launch(void* const* d_in, const int* in_sizes, int n_in,
                              void* d_out, int out_size)
{
    const float* z0 = (const float*)d_in[0];
    const float* W1 = (const float*)d_in[1];
    const float* b1 = (const float*)d_in[2];
    const float* W2 = (const float*)d_in[3];
    const float* b2 = (const float*)d_in[4];
    const float* t0 = (const float*)d_in[5];
    const float* t1 = (const float*)d_in[6];
    float* dout = (float*)d_out;
    (void)in_sizes; (void)n_in; (void)out_size;

    cudaFuncSetAttribute(gemm_tc, cudaFuncAttributeMaxDynamicSharedMemorySize, SMEM_TOT);

    convert_z<<<(BATCH*DIM + 255)/256, 256>>>(z0);
    convert_w<<<(HIDN*DIM + 255)/256, 256>>>(W1, W2);

    dim3 gH(HIDN/BN, BATCH/BM, 1);   // 16 x 64      = 1024 CTAs
    dim3 gK(DIM/BN,  BATCH/BM, 4);   //  4 x 64 x 4  = 1024 CTAs (split-K=4)

    const float Wc[4]   = {1.f/6.f, 1.f/3.f, 1.f/3.f, 1.f/6.f};
    const float Ac[4]   = {0.5f, 0.5f, 1.0f, 0.f};
    const float Coff[4] = {0.f, 0.5f, 0.5f, 1.0f};

    for (int i = 0; i < NSTEPS; i++){
        for (int s = 0; s < 4; s++){
            gemm_tc<<<gH, 256, SMEM_TOT>>>(b1, b2, t0, t1, dout,
                                           0, (float)i, Coff[s],
                                           0.f, 0.f, 0, 0, 0);
            const int fin  = (s == 3);
            const int tOut = (fin && i == NSTEPS-1);
            gemm_tc<<<gK, 256, SMEM_TOT>>>(b1, b2, t0, t1, dout,
                                           1, (float)i, 0.f,
                                           Wc[s], Ac[s], (s > 0), fin, tOut);
        }
    }
}

// round 11
// speedup vs baseline: 1.0763x; 1.0763x over previous
#include <cuda_runtime.h>
#include <cuda_bf16.h>
#include <cstdint>

#define BATCH 4096
#define DIM   512
#define HIDN  2048
#define NSTEPS 20

#define BM 64
#define BN 128
#define BK 32
#define MI 2
#define NI 4
#define SPITCH 40          // bf16 per smem row (80B) — 16B-aligned, LDSM conflict-free
#define ROWB (SPITCH*2)

#define ASZ (BM*ROWB)      // 5120
#define BSZ (BN*ROWB)      // 10240
#define SMA 1024
#define SMB (SMA + 3*ASZ)
#define SMEM_TOT (SMB + 3*BSZ)   // 47104  (x4 CTAs = 188KB <= 227KB)

// ---------------- persistent scratch ----------------
__device__ __align__(256) float          g_zcur[BATCH*DIM];
__device__ __align__(256) float          g_zacc[BATCH*DIM];
__device__ __align__(256) float          g_kp[4][BATCH*DIM];   // split-K partials
__device__ __align__(256) __nv_bfloat16  g_zb[BATCH*DIM];
__device__ __align__(256) __nv_bfloat16  g_hid[BATCH*HIDN];
__device__ __align__(256) __nv_bfloat16  g_w1t[HIDN*DIM];      // [n][k]
__device__ __align__(256) float          g_w1last[HIDN];
__device__ __align__(256) __nv_bfloat16  g_w2t[DIM*HIDN];      // [n][k]

// ---------------- converts ----------------
__global__ void convert_z(const float* __restrict__ z0){
    int i = blockIdx.x*blockDim.x + threadIdx.x;
    if (i < BATCH*DIM){
        float v = z0[i];
        g_zcur[i] = v;
        g_zb[i]   = __float2bfloat16(v);
    }
}
__global__ void convert_w(const float* __restrict__ W1, const float* __restrict__ W2){
    int i = blockIdx.x*blockDim.x + threadIdx.x;
    if (i < HIDN*DIM){
        int n = i / DIM, k = i % DIM;
        g_w1t[i] = __float2bfloat16(W1[(size_t)k*HIDN + n]);
    }
    if (i < DIM*HIDN){
        int n = i / HIDN, k = i % HIDN;
        g_w2t[i] = __float2bfloat16(W2[(size_t)k*DIM + n]);
    }
    if (i < HIDN) g_w1last[i] = W1[(size_t)DIM*HIDN + i];
}

// ---------------- helpers ----------------
__device__ __forceinline__ void cpa16(uint32_t s, const void* g){
    asm volatile("cp.async.cg.shared.global [%0], [%1], 16;\n" :: "r"(s), "l"(g));
}
__device__ __forceinline__ void ldsm4(uint32_t& r0, uint32_t& r1, uint32_t& r2, uint32_t& r3,
                                      uint32_t addr){
    asm volatile("ldmatrix.sync.aligned.m8n8.x4.shared.b16 {%0,%1,%2,%3}, [%4];"
                 : "=r"(r0), "=r"(r1), "=r"(r2), "=r"(r3) : "r"(addr));
}
__device__ __forceinline__ uint32_t smem_u32(const void* p){
    uint32_t a;
    asm("{ .reg .u64 t; cvta.to.shared.u64 t, %1; cvt.u32.u64 %0, t; }" : "=r"(a) : "l"(p));
    return a;
}
#define MMA16816(acc, af, bf)                                                     \
    asm volatile(                                                                 \
        "mma.sync.aligned.m16n8k16.row.col.f32.bf16.bf16.f32 "                    \
        "{%0,%1,%2,%3}, {%4,%5,%6,%7}, {%8,%9}, {%0,%1,%2,%3};\n"                 \
        : "+f"(acc[0]), "+f"(acc[1]), "+f"(acc[2]), "+f"(acc[3])                  \
        : "r"(af[0]), "r"(af[1]), "r"(af[2]), "r"(af[3]), "r"(bf[0]), "r"(bf[1]))

// ---------------- fused GEMM ----------------
// CTA 64x128, 256 thr (8 warps: 2M x 4N, warp 32x32), BK=32, 3-stage, K-extent 512.
// epi==0: g_hid = tanh(g_zb @ g_w1t^T + b1 + t*w1last)
// epi==1: g_kp[blockIdx.z] = partial(g_hid @ g_w2t^T), K = [z*512, z*512+512)
__global__ void __launch_bounds__(256, 4)
gemm_tc(const float* __restrict__ b1,
        const float* __restrict__ t0p, const float* __restrict__ t1p,
        int epi, float stepF, float cOff)
{
    extern __shared__ char smem[];
    const uint32_t sb = smem_u32(smem);
    float* biasS = (float*)smem;

    const int tid  = threadIdx.x;
    const int lane = tid & 31, w = tid >> 5;
    const uint32_t bm = blockIdx.y * BM, bn = blockIdx.x * BN;

    const __nv_bfloat16* A; const __nv_bfloat16* B; uint32_t Kd, kOff;
    float* kp = nullptr;
    if (epi == 0){ A = g_zb;  B = g_w1t; Kd = DIM;  kOff = 0; }
    else {
        A = g_hid; B = g_w2t; Kd = HIDN;
        kOff = blockIdx.z * 512u;
        kp   = g_kp[blockIdx.z];
    }
    constexpr int NT = 512 / BK;    // 16 for both paths

    const int wm = (w >> 2) * 32;
    const int wn = (w & 3)  * 32;

    const int lr = lane & 7;
    const int lm = (lane >> 3) & 1;
    const int lk = (lane >> 4) & 1;
    const uint32_t aBase = sb + SMA + (uint32_t)((wm + lr + lm*8)*SPITCH + lk*8)*2;
    const uint32_t bBase = sb + SMB + (uint32_t)((wn + lr + lm*8)*SPITCH + lk*8)*2;

    // 32-bit global offsets (element units)
    const uint32_t aRow = bm + (uint32_t)(tid >> 2);
    const uint32_t aCol = (uint32_t)(tid & 3) * 8u;
    const uint32_t aG0  = aRow * Kd + kOff + aCol;
    const uint32_t sAoff = (uint32_t)(tid >> 2) * ROWB + (uint32_t)(tid & 3) * 16u;

    auto loadChunk = [&](int c){
        const int s = c % 3;
        const uint32_t kc = (uint32_t)c * BK;
        // A: 64 rows x 4 x 16B (1 vector per thread)
        cpa16(sb + SMA + s*ASZ + sAoff, A + aG0 + kc);
        // B: 128 rows x 4 x 16B (2 vectors per thread)
        const uint32_t sB = sb + SMB + s*BSZ;
        #pragma unroll
        for (int r = 0; r < 2; r++){
            uint32_t v = (uint32_t)tid + r*256u;
            uint32_t row = v >> 2, col = v & 3;
            cpa16(sB + row*ROWB + col*16u,
                  B + (bn + row)*Kd + kOff + kc + col*8u);
        }
        asm volatile("cp.async.commit_group;\n");
    };

    loadChunk(0);
    loadChunk(1);

    // bias -> smem (GEMM1 only)
    if (epi == 0 && tid < BN){
        const float t0v = __ldg(t0p), t1v = __ldg(t1p);
        const float hh  = (t1v - t0v) / (float)NSTEPS;
        float t = t0v + (stepF + cOff) * hh;
        biasS[tid] = __ldg(&b1[bn + tid]) + t * g_w1last[bn + tid];
    }

    float acc[MI][NI][4];
    #pragma unroll
    for (int a=0;a<MI;a++)
        #pragma unroll
        for (int b=0;b<NI;b++)
            #pragma unroll
            for (int c=0;c<4;c++) acc[a][b][c] = 0.f;

    for (int kt = 0; kt < NT; kt++){
        if (kt < NT-1) asm volatile("cp.async.wait_group 1;\n");
        else           asm volatile("cp.async.wait_group 0;\n");
        __syncthreads();
        if (kt + 2 < NT) loadChunk(kt + 2);   // writes stage (kt+2)%3 == (kt-1)%3: safe after sync

        const int s = kt % 3;
        const uint32_t aAddr = aBase + s*ASZ;
        const uint32_t bAddr = bBase + s*BSZ;

        #pragma unroll
        for (int kki = 0; kki < 2; kki++){
            const uint32_t koff = (uint32_t)(kki*32);   // 16 bf16 = 32B
            uint32_t af[MI][4], bf[NI][2];
            #pragma unroll
            for (int mi = 0; mi < MI; mi++)
                ldsm4(af[mi][0], af[mi][1], af[mi][2], af[mi][3],
                      aAddr + (uint32_t)(mi*16*ROWB) + koff);
            #pragma unroll
            for (int nh = 0; nh < NI/2; nh++){
                uint32_t r0, r1, r2, r3;
                ldsm4(r0, r1, r2, r3, bAddr + (uint32_t)(nh*16*ROWB) + koff);
                bf[2*nh  ][0] = r0; bf[2*nh  ][1] = r2;
                bf[2*nh+1][0] = r1; bf[2*nh+1][1] = r3;
            }
            #pragma unroll
            for (int mi = 0; mi < MI; mi++)
                #pragma unroll
                for (int ni = 0; ni < NI; ni++)
                    MMA16816(acc[mi][ni], af[mi], bf[ni]);
        }
    }

    // ---------------- epilogue ----------------
    const int g  = lane >> 2;
    const int tq = lane & 3;
    const uint32_t ldo = (epi == 0) ? (uint32_t)HIDN : (uint32_t)DIM;
    const uint32_t rowBase = bm + wm + g;
    const uint32_t colBase = bn + wn + tq*2;

    #pragma unroll
    for (int mi = 0; mi < MI; mi++)
        #pragma unroll
        for (int ni = 0; ni < NI; ni++){
            const uint32_t col = colBase + ni*8;
            #pragma unroll
            for (int half = 0; half < 2; half++){
                const uint32_t row = rowBase + mi*16 + half*8;
                const uint32_t idx = row * ldo + col;
                float v0 = acc[mi][ni][half*2+0];
                float v1 = acc[mi][ni][half*2+1];
                if (epi == 0){
                    v0 += biasS[col - bn]; v1 += biasS[col - bn + 1];
                    float th0, th1;
                    asm("tanh.approx.f32 %0, %1;" : "=f"(th0) : "f"(v0));
                    asm("tanh.approx.f32 %0, %1;" : "=f"(th1) : "f"(v1));
                    *(__nv_bfloat162*)(&g_hid[idx]) = __floats2bfloat162_rn(th0, th1);
                } else {
                    *(float2*)(&kp[idx]) = make_float2(v0, v1);
                }
            }
        }
}

// ---------------- RK4 elementwise update ----------------
__global__ void __launch_bounds__(256)
rk4_update(const float* __restrict__ b2,
           const float* __restrict__ t0p, const float* __restrict__ t1p,
           float* __restrict__ dout,
           float wcoef, float acoef, int accPrev, int finalStage, int toOut)
{
    const int i4 = blockIdx.x*256 + threadIdx.x;
    const int base = i4 * 4;
    const float hh = (__ldg(t1p) - __ldg(t0p)) / (float)NSTEPS;
    const float wh = wcoef * hh, ah = acoef * hh;

    float4 k0 = *(const float4*)(&g_kp[0][base]);
    float4 k1 = *(const float4*)(&g_kp[1][base]);
    float4 k2 = *(const float4*)(&g_kp[2][base]);
    float4 k3 = *(const float4*)(&g_kp[3][base]);
    const float4 bb = *(const float4*)(&b2[base & (DIM-1)]);
    float4 k = make_float4(k0.x+k1.x+k2.x+k3.x+bb.x,
                           k0.y+k1.y+k2.y+k3.y+bb.y,
                           k0.z+k1.z+k2.z+k3.z+bb.z,
                           k0.w+k1.w+k2.w+k3.w+bb.w);

    float4 za;
    if (accPrev) za = *(const float4*)(&g_zacc[base]);
    else         za = make_float4(0.f,0.f,0.f,0.f);
    za.x += wh*k.x; za.y += wh*k.y; za.z += wh*k.z; za.w += wh*k.w;
    *(float4*)(&g_zacc[base]) = za;

    float4 zc = *(const float4*)(&g_zcur[base]);
    float4 zn;
    if (finalStage){
        zn = make_float4(zc.x+za.x, zc.y+za.y, zc.z+za.z, zc.w+za.w);
        if (toOut) *(float4*)(&dout[base]) = zn;
        else       *(float4*)(&g_zcur[base]) = zn;
    } else {
        zn = make_float4(zc.x+ah*k.x, zc.y+ah*k.y, zc.z+ah*k.z, zc.w+ah*k.w);
    }
    *(__nv_bfloat162*)(&g_zb[base])   = __floats2bfloat162_rn(zn.x, zn.y);
    *(__nv_bfloat162*)(&g_zb[base+2]) = __floats2bfloat162_rn(zn.z, zn.w);
}

// ---------------- launcher ----------------
extern "C" void kernel_launch(void* const* d_in, const int* in_sizes, int n_in,
                              void* d_out, int out_size)
{
    const float* z0 = (const float*)d_in[0];
    const float* W1 = (const float*)d_in[1];
    const float* b1 = (const float*)d_in[2];
    const float* W2 = (const float*)d_in[3];
    const float* b2 = (const float*)d_in[4];
    const float* t0 = (const float*)d_in[5];
    const float* t1 = (const float*)d_in[6];
    float* dout = (float*)d_out;
    (void)in_sizes; (void)n_in; (void)out_size;

    cudaFuncSetAttribute(gemm_tc, cudaFuncAttributeMaxDynamicSharedMemorySize, SMEM_TOT);

    convert_z<<<(BATCH*DIM + 255)/256, 256>>>(z0);
    convert_w<<<(HIDN*DIM + 255)/256, 256>>>(W1, W2);

    dim3 gH(HIDN/BN, BATCH/BM, 1);   // 16 x 64      = 1024 CTAs
    dim3 gK(DIM/BN,  BATCH/BM, 4);   //  4 x 64 x 4  = 1024 CTAs (split-K=4)
    const int gE = (BATCH*DIM/4 + 255)/256;  // 2048 CTAs

    const float Wc[4]   = {1.f/6.f, 1.f/3.f, 1.f/3.f, 1.f/6.f};
    const float Ac[4]   = {0.5f, 0.5f, 1.0f, 0.f};
    const float Coff[4] = {0.f, 0.5f, 0.5f, 1.0f};

    for (int i = 0; i < NSTEPS; i++){
        for (int s = 0; s < 4; s++){
            gemm_tc<<<gH, 256, SMEM_TOT>>>(b1, t0, t1, 0, (float)i, Coff[s]);
            gemm_tc<<<gK, 256, SMEM_TOT>>>(b1, t0, t1, 1, (float)i, 0.f);
            const int fin  = (s == 3);
            const int tOut = (fin && i == NSTEPS-1);
            rk4_update<<<gE, 256>>>(b2, t0, t1, dout,
                                    Wc[s], Ac[s], (s > 0), fin, tOut);
        }
    }
}